// round 9
// baseline (speedup 1.0000x reference)
#include <cuda_runtime.h>
#include <math.h>

// Problem constants (fixed shapes: x is (8,1,64,64) float32)
#define B_DIM 8
#define H_DIM 64
#define W_DIM 64
#define N_PIX (H_DIM * W_DIM)          // 4096
#define M0_CONST 0.01f

#define NOFF (127 * 127)               // 16129 offsets, sorted by d2
#define MAXD2 (63 * 63 * 2)
#define SEG 64                         // entries per segment
#define NSEG 4                         // threads per pixel
#define COVER (SEG * NSEG)             // 256 staged entries
#define PIXB 256                       // pixels per block
#define NTHR (PIXB * NSEG)             // 1024 threads
#define ZSLOT N_PIX                    // smem slot holding 0.0f for OOB lanes

struct OffTable { unsigned int v[NOFF]; };

constexpr OffTable make_table() {
    OffTable t{};
    int bins[MAXD2 + 1] = {};
    for (int dy = -63; dy <= 63; ++dy)
        for (int dx = -63; dx <= 63; ++dx)
            bins[dy * dy + dx * dx]++;
    int acc = 0;
    for (int d = 0; d <= MAXD2; ++d) { int c = bins[d]; bins[d] = acc; acc += c; }
    for (int dy = -63; dy <= 63; ++dy)
        for (int dx = -63; dx <= 63; ++dx) {
            int d2 = dy * dy + dx * dx;
            t.v[bins[d2]++] = ((unsigned)d2 << 16)
                            | ((unsigned)(dy + 63) << 8)
                            | (unsigned)(dx + 63);
        }
    return t;
}

__device__ constexpr OffTable g_off = make_table();

// One block = 256 pixels x 4 segment-threads. Warp = 32 same-row pixels,
// one segment (seg is warp-uniform) -> warp-uniform rescan skipping.
__global__ __launch_bounds__(NTHR) void dtm_kernel(const float* __restrict__ xin,
                                                   float* __restrict__ out) {
    __shared__ __align__(16) float          simg[N_PIX + 4]; // image + zero slot
    __shared__ __align__(16) float          s_d2[COVER];
    __shared__ __align__(16) unsigned short s_off[COVER];
    __shared__ __align__(16) float          swarp[32];       // per-warp sums
    __shared__ float                        sW[NTHR];        // seg masses
    __shared__ float                        sS[NTHR];        // seg contributions

    const int tid   = threadIdx.x;
    const int lane  = tid & 31;
    const int wid   = tid >> 5;
    const int batch = blockIdx.x >> 4;
    const int base  = (blockIdx.x & 15) << 8;    // pixel slab start
    const float* img = xin + batch * N_PIX;

    // ---- Prologue: image -> smem (one float4/thread) + mass partial sum ----
    float part;
    {
        float4 v = ((const float4*)img)[tid];
        ((float4*)simg)[tid] = v;
        part = (v.x + v.y) + (v.z + v.w);
    }
    if (tid == 0) simg[ZSLOT] = 0.0f;
    if (tid < COVER) {                           // stage hot table prefix
        unsigned p = g_off.v[tid];
        s_d2[tid]  = (float)(p >> 16);
        s_off[tid] = (unsigned short)(p & 0xFFFFu);
    }
    #pragma unroll
    for (int o = 16; o > 0; o >>= 1)
        part += __shfl_xor_sync(0xFFFFFFFFu, part, o);
    if (lane == 0) swarp[wid] = part;
    __syncthreads();                             // B1

    float total = 0.0f;
    #pragma unroll
    for (int j = 0; j < 8; ++j) {
        float4 a = ((const float4*)swarp)[j];
        total += (a.x + a.y) + (a.z + a.w);
    }
    const float m = M0_CONST * total;

    const int pix = tid & (PIXB - 1);
    const int q   = tid >> 8;                    // segment id (warp-uniform)
    const int i   = base + pix;
    const int y   = i >> 6;
    const int x   = i & 63;
    // Packed base: Qm = basep + e gives ((y+dy)<<8)+(x+dx); valid iff the
    // masked bits (sign / carry spill included) are all zero.
    const int basep = ((y << 8) | x) - 0x3F3F;
    const int k0 = q * SEG;

    // ---- Phase 1: unclipped segment mass (branch-free, chain-free) ----
    float a0 = 0.f, a1 = 0.f, a2 = 0.f, a3 = 0.f;
    #pragma unroll
    for (int g = 0; g < SEG / 4; ++g) {
        const int k = k0 + 4 * g;
        const uint2 ov = *reinterpret_cast<const uint2*>(s_off + k); // broadcast
        const int Q0 = basep + (int)(ov.x & 0xFFFFu);
        const int Q1 = basep + (int)(ov.x >> 16);
        const int Q2 = basep + (int)(ov.y & 0xFFFFu);
        const int Q3 = basep + (int)(ov.y >> 16);
        a0 += simg[((Q0 & ~0x3F3F) == 0) ? Q0 - (Q0 >> 8) * 192 : ZSLOT];
        a1 += simg[((Q1 & ~0x3F3F) == 0) ? Q1 - (Q1 >> 8) * 192 : ZSLOT];
        a2 += simg[((Q2 & ~0x3F3F) == 0) ? Q2 - (Q2 >> 8) * 192 : ZSLOT];
        a3 += simg[((Q3 & ~0x3F3F) == 0) ? Q3 - (Q3 >> 8) * 192 : ZSLOT];
    }
    const float W = (a0 + a1) + (a2 + a3);
    sW[q * PIXB + pix] = W;                      // conflict-free store
    __syncthreads();                             // B2

    // ---- Phase 2: exclusive prefix of segment masses for this pixel ----
    float P = 0.0f;
    if (q > 0) P += sW[pix];
    if (q > 1) P += sW[PIXB + pix];
    if (q > 2) P += sW[2 * PIXB + pix];
    const float rem = m - P;

    // ---- Phase 3: clipped rescan (skipped warp-uniformly when saturated) --
    float c = 0.0f;
    if (!__all_sync(0xFFFFFFFFu, rem <= 0.0f)) {
        float s0 = 0.f, s1 = 0.f, s2 = 0.f, s3 = 0.f;
        float r = rem;
        #pragma unroll
        for (int g = 0; g < SEG / 4; ++g) {
            const int k = k0 + 4 * g;
            const uint2  ov = *reinterpret_cast<const uint2*>(s_off + k);
            const float4 dd = *reinterpret_cast<const float4*>(s_d2 + k);
            const int Q0 = basep + (int)(ov.x & 0xFFFFu);
            const int Q1 = basep + (int)(ov.x >> 16);
            const int Q2 = basep + (int)(ov.y & 0xFFFFu);
            const int Q3 = basep + (int)(ov.y >> 16);
            const float w0 = simg[((Q0 & ~0x3F3F) == 0) ? Q0 - (Q0 >> 8) * 192 : ZSLOT];
            const float w1 = simg[((Q1 & ~0x3F3F) == 0) ? Q1 - (Q1 >> 8) * 192 : ZSLOT];
            const float w2 = simg[((Q2 & ~0x3F3F) == 0) ? Q2 - (Q2 >> 8) * 192 : ZSLOT];
            const float w3 = simg[((Q3 & ~0x3F3F) == 0) ? Q3 - (Q3 >> 8) * 192 : ZSLOT];
            const float p1 = w0;
            const float p2 = p1 + w1;
            const float p3 = p2 + w2;
            const float gs = p3 + w3;
            s0 = fmaf(fmaxf(0.f, fminf(w0, r)),      dd.x, s0);
            s1 = fmaf(fmaxf(0.f, fminf(w1, r - p1)), dd.y, s1);
            s2 = fmaf(fmaxf(0.f, fminf(w2, r - p2)), dd.z, s2);
            s3 = fmaf(fmaxf(0.f, fminf(w3, r - p3)), dd.w, s3);
            r -= gs;                               // only serial dependence
        }
        c = (s0 + s1) + (s2 + s3);
    }

    // ---- Fallback past the staged prefix (seg3 warps; ~never fires) ------
    if (q == 3) {
        float rr = rem - W;                        // m - F(COVER)
        if (__any_sync(0xFFFFFFFFu, rr > 0.0f)) {
            for (int k = COVER; k < NOFF; ++k) {
                const unsigned p = g_off.v[k];
                const int Qm = basep + (int)(p & 0xFFFFu);
                if ((Qm & ~0x3F3F) == 0) {
                    const float w   = simg[Qm - (Qm >> 8) * 192];
                    const float eff = fmaxf(0.f, fminf(w, rr));
                    c = fmaf(eff, (float)(p >> 16), c);
                    rr -= w;
                }
                if (__all_sync(0xFFFFFFFFu, rr <= 0.0f)) break;
            }
        }
    }

    sS[q * PIXB + pix] = c;
    __syncthreads();                             // B3

    // ---- Phase 4: combine 4 segment contributions, finalize -------------
    if (q == 0) {
        const float s = (sS[pix] + sS[PIXB + pix])
                      + (sS[2 * PIXB + pix] + sS[3 * PIXB + pix]);
        const float result = (total > 0.0f) ? sqrtf(s / m) : 0.0f;
        out[batch * N_PIX + i] = result;
    }
}

extern "C" void kernel_launch(void* const* d_in, const int* in_sizes, int n_in,
                              void* d_out, int out_size) {
    const float* xin = (const float*)d_in[0];
    float* out = (float*)d_out;
    (void)in_sizes; (void)n_in; (void)out_size;
    dtm_kernel<<<B_DIM * (N_PIX / PIXB), NTHR>>>(xin, out);
}

// round 11
// speedup vs baseline: 2.5467x; 2.5467x over previous
#include <cuda_runtime.h>
#include <math.h>

// Problem constants (fixed shapes: x is (8,1,64,64) float32)
#define B_DIM 8
#define H_DIM 64
#define W_DIM 64
#define N_PIX (H_DIM * W_DIM)          // 4096
#define M0_CONST 0.01f

#define NOFF (127 * 127)               // 16129 offsets, sorted by d2
#define MAXD2 (63 * 63 * 2)
#define HOT 256                        // fully-unrolled hot entries
#define HY 10                          // halo rows (top & bottom)
#define HX 12                          // halo cols left (right halo = 12)
#define PSTR 88                        // padded row stride (12+64+12)
#define PROWS 84                       // 10+64+10
#define PSZ (PROWS * PSTR)             // 7392 floats = 29.6 KB

struct OffTable { unsigned int v[NOFF]; };

constexpr OffTable make_table() {
    OffTable t{};
    int bins[MAXD2 + 1] = {};
    for (int dy = -63; dy <= 63; ++dy)
        for (int dx = -63; dx <= 63; ++dx)
            bins[dy * dy + dx * dx]++;
    int acc = 0;
    for (int d = 0; d <= MAXD2; ++d) { int c = bins[d]; bins[d] = acc; acc += c; }
    for (int dy = -63; dy <= 63; ++dy)
        for (int dx = -63; dx <= 63; ++dx) {
            int d2 = dy * dy + dx * dx;
            t.v[bins[d2]++] = ((unsigned)d2 << 16)
                            | ((unsigned)(dy + 63) << 8)
                            | (unsigned)(dx + 63);
        }
    return t;
}

__device__ constexpr OffTable g_off = make_table();   // fallback path only

// Hot prefix as compile-time constants: padded-smem offset + float d2.
struct Hot { int c[HOT]; float d2[HOT]; };
constexpr Hot make_hot() {
    Hot h{};
    OffTable t = make_table();
    for (int k = 0; k < HOT; ++k) {
        int dy = (int)((t.v[k] >> 8) & 255u) - 63;
        int dx = (int)(t.v[k] & 255u) - 63;
        h.c[k]  = (dy + HY) * PSTR + (dx + HX);
        h.d2[k] = (float)(t.v[k] >> 16);
    }
    return h;
}
__device__ constexpr Hot g_hot = make_hot();

// Halo must cover every hot entry: |dy| <= HY, |dx| <= HX.
constexpr bool halo_ok() {
    OffTable t = make_table();
    for (int k = 0; k < HOT; ++k) {
        int dy = (int)((t.v[k] >> 8) & 255u) - 63;
        int dx = (int)(t.v[k] & 255u) - 63;
        if (dy < -HY || dy > HY || dx < -HX || dx > HX) return false;
    }
    return true;
}
static_assert(halo_ok(), "halo too small for HOT prefix");

// One block = 256 pixels (4 rows) of one batch image. The image lives in a
// zero-padded smem buffer, so every hot-loop access is LDS [base + imm] with
// no bounds test; OOB probes read halo zeros (exact no-op in the clip).
__global__ __launch_bounds__(256) void dtm_kernel(const float* __restrict__ xin,
                                                  float* __restrict__ out) {
    __shared__ __align__(16) float pimg[PSZ];
    __shared__ float swarp[8];

    const int tid   = threadIdx.x;
    const int lane  = tid & 31;
    const int wid   = tid >> 5;
    const int batch = blockIdx.x >> 4;
    const int base  = (blockIdx.x & 15) << 8;    // pixel slab start
    const float* img = xin + batch * N_PIX;

    // Issue the 4 image loads first (long latency), then zero the pad.
    const float4 v0 = ((const float4*)img)[tid];
    const float4 v1 = ((const float4*)img)[tid + 256];
    const float4 v2 = ((const float4*)img)[tid + 512];
    const float4 v3 = ((const float4*)img)[tid + 768];

    const float4 z4 = make_float4(0.f, 0.f, 0.f, 0.f);
    #pragma unroll
    for (int j = 0; j < 8; ++j) {
        const int idx = tid + j * 256;
        if (idx < PSZ / 4) ((float4*)pimg)[idx] = z4;
    }
    __syncthreads();                              // pad zeroed

    // Scatter image into padded layout (16B-aligned stores) + mass partial.
    const int y0 = tid >> 4;                      // row of elements 4*tid..
    const int x0 = (tid & 15) << 2;               // col (multiple of 4)
    *(float4*)&pimg[(y0 + HY)      * PSTR + x0 + HX] = v0;
    *(float4*)&pimg[(y0 + HY + 16) * PSTR + x0 + HX] = v1;
    *(float4*)&pimg[(y0 + HY + 32) * PSTR + x0 + HX] = v2;
    *(float4*)&pimg[(y0 + HY + 48) * PSTR + x0 + HX] = v3;

    float part = ((v0.x + v0.y) + (v0.z + v0.w)) + ((v1.x + v1.y) + (v1.z + v1.w))
               + ((v2.x + v2.y) + (v2.z + v2.w)) + ((v3.x + v3.y) + (v3.z + v3.w));
    #pragma unroll
    for (int o = 16; o > 0; o >>= 1)
        part += __shfl_xor_sync(0xFFFFFFFFu, part, o);
    if (lane == 0) swarp[wid] = part;
    __syncthreads();                              // image + partials published

    float total;
    {
        float4 a = ((const float4*)swarp)[0];
        float4 b = ((const float4*)swarp)[1];
        total = ((a.x + a.y) + (a.z + a.w)) + ((b.x + b.y) + (b.z + b.w));
    }
    const float m = M0_CONST * total;

    const int i = base + tid;                     // pixel index within image
    const int y = i >> 6;
    const int x = i & 63;
    const int bi = y * PSTR + x;                  // halo shift lives in g_hot.c

    float r  = m;                                 // remaining mass
    float s0 = 0.f, s1 = 0.f, s2 = 0.f, s3 = 0.f;

    if (m > 0.0f) {
        #pragma unroll
        for (int ch = 0; ch < HOT / 16; ++ch) {
            #pragma unroll
            for (int g = 0; g < 4; ++g) {
                const int k = ch * 16 + g * 4;
                const float w0 = pimg[bi + g_hot.c[k]];      // LDS [R+imm]
                const float w1 = pimg[bi + g_hot.c[k + 1]];
                const float w2 = pimg[bi + g_hot.c[k + 2]];
                const float w3 = pimg[bi + g_hot.c[k + 3]];
                const float p1 = w0;
                const float p2 = p1 + w1;
                const float p3 = p2 + w2;
                const float gs = p3 + w3;
                s0 = fmaf(fmaxf(0.f, fminf(w0, r)),      g_hot.d2[k],     s0);
                s1 = fmaf(fmaxf(0.f, fminf(w1, r - p1)), g_hot.d2[k + 1], s1);
                s2 = fmaf(fmaxf(0.f, fminf(w2, r - p2)), g_hot.d2[k + 2], s2);
                s3 = fmaf(fmaxf(0.f, fminf(w3, r - p3)), g_hot.d2[k + 3], s3);
                r -= gs;                          // only cross-entry dependence
            }
            if (__all_sync(0xFFFFFFFFu, r <= 0.0f)) break;   // warp-uniform
        }

        // Fallback past the hot prefix (pathological inputs only; reads the
        // image from global/L2 since the padded halo doesn't reach that far).
        if (__any_sync(0xFFFFFFFFu, r > 0.0f)) {
            for (int k = HOT; k < NOFF; ++k) {
                const unsigned p = g_off.v[k];
                const int ny = y + (int)((p >> 8) & 255u) - 63;
                const int nx = x + (int)(p & 255u) - 63;
                if ((unsigned)ny < (unsigned)H_DIM &&
                    (unsigned)nx < (unsigned)W_DIM) {
                    const float w   = img[(ny << 6) | nx];
                    const float eff = fmaxf(0.f, fminf(w, r));
                    s0 = fmaf(eff, (float)(p >> 16), s0);
                    r -= w;
                }
                if (__all_sync(0xFFFFFFFFu, r <= 0.0f)) break;
            }
        }
    }

    const float s = (s0 + s1) + (s2 + s3);
    const float result = (total > 0.0f) ? sqrtf(s / m) : 0.0f;
    out[batch * N_PIX + i] = result;
}

extern "C" void kernel_launch(void* const* d_in, const int* in_sizes, int n_in,
                              void* d_out, int out_size) {
    const float* xin = (const float*)d_in[0];
    float* out = (float*)d_out;
    (void)in_sizes; (void)n_in; (void)out_size;
    dtm_kernel<<<B_DIM * (N_PIX / 256), 256>>>(xin, out);
}